// round 9
// baseline (speedup 1.0000x reference)
#include <cuda_runtime.h>
#include <cuda_bf16.h>
#include <cstdint>

// Problem constants (fixed shapes per reference)
#define BATCH 16
#define N1    1024
#define NP    4096
#define D1    256
#define D2    128
#define DIN   384          // D1 + D2
#define HID   256
#define MTOT  (BATCH * NP) // 65536
#define F32_EPS 1.1920929e-07f
#define BN_EPS  1e-5f

// Scratch (static device globals: allocation-free)
__device__ __nv_bfloat16 g_xh[MTOT * DIN];   // concat input, hi bf16
__device__ __nv_bfloat16 g_xl[MTOT * DIN];   // concat input, lo bf16
__device__ float         g_y [MTOT * HID];   // layer-1 pre-BN output (fp32)
__device__ __nv_bfloat16 g_yh[MTOT * HID];   // bn(relu(y)) hi
__device__ __nv_bfloat16 g_yl[MTOT * HID];   // bn(relu(y)) lo
__device__ __nv_bfloat16 g_w1h[HID * DIN], g_w1l[HID * DIN];
__device__ __nv_bfloat16 g_w2h[HID * HID], g_w2l[HID * HID];
__device__ float g_stats[4 * HID];   // [sum1, sumsq1, sum2, sumsq2]

// ---------------------------------------------------------------------------
// helpers
// ---------------------------------------------------------------------------
__device__ __forceinline__ uint32_t smem_u32(const void* p) {
    uint32_t a;
    asm("{ .reg .u64 t; cvta.to.shared.u64 t, %1; cvt.u32.u64 %0, t; }" : "=r"(a) : "l"(p));
    return a;
}
__device__ __forceinline__ uint32_t sw64(uint32_t off) {   // 64B-row swizzle
    return off ^ ((off >> 3) & 0x30);
}
// Split two floats into packed hi/lo bf16x2 words.
__device__ __forceinline__ uint32_t pack2(float x, float y, uint32_t& lo) {
    __nv_bfloat16 hx = __float2bfloat16_rn(x);
    __nv_bfloat16 hy = __float2bfloat16_rn(y);
    __nv_bfloat16 lx = __float2bfloat16_rn(x - __bfloat162float(hx));
    __nv_bfloat16 ly = __float2bfloat16_rn(y - __bfloat162float(hy));
    lo = ((uint32_t)__bfloat16_as_ushort(ly) << 16) | __bfloat16_as_ushort(lx);
    return ((uint32_t)__bfloat16_as_ushort(hy) << 16) | __bfloat16_as_ushort(hx);
}
__device__ __forceinline__ void cp16(uint32_t s, const void* g) {
    asm volatile("cp.async.cg.shared.global [%0], [%1], 16;" :: "r"(s), "l"(g));
}
__device__ __forceinline__ void ldsm4(unsigned* r, uint32_t addr) {
    asm volatile("ldmatrix.sync.aligned.m8n8.x4.shared.b16 {%0,%1,%2,%3}, [%4];"
                 : "=r"(r[0]), "=r"(r[1]), "=r"(r[2]), "=r"(r[3]) : "r"(addr));
}
__device__ __forceinline__ void mma_b(float* d, const unsigned* a, unsigned b0, unsigned b1) {
    asm volatile(
        "mma.sync.aligned.m16n8k16.row.col.f32.bf16.bf16.f32 "
        "{%0,%1,%2,%3}, {%4,%5,%6,%7}, {%8,%9}, {%0,%1,%2,%3};\n"
        : "+f"(d[0]), "+f"(d[1]), "+f"(d[2]), "+f"(d[3])
        : "r"(a[0]), "r"(a[1]), "r"(a[2]), "r"(a[3]), "r"(b0), "r"(b1));
}

// ---------------------------------------------------------------------------
// 3-NN inverse-distance interpolation + concat; writes split bf16 directly.
// Block (0,0) also zeroes g_stats.
__global__ __launch_bounds__(256) void interp_kernel(
    const float* __restrict__ xyz1, const float* __restrict__ xyz2,
    const float* __restrict__ f1,   const float* __restrict__ f2)
{
    __shared__ float sx[N1 * 3];
    const int b = blockIdx.y;
    if (b == 0 && blockIdx.x == 0)
        for (int i = threadIdx.x; i < 4 * HID; i += 256) g_stats[i] = 0.0f;
    const float* x1b = xyz1 + (size_t)b * N1 * 3;
    for (int i = threadIdx.x; i < N1 * 3; i += blockDim.x) sx[i] = x1b[i];
    __syncthreads();

    const int warp = threadIdx.x >> 5, lane = threadIdx.x & 31;
    const int qbase = blockIdx.x * 32 + warp * 4;
    const float* f1b = f1 + (size_t)b * N1 * D1;

    for (int q = 0; q < 4; ++q) {
        const int j = qbase + q;
        const float* qp = xyz2 + ((size_t)b * NP + j) * 3;
        const float qx = qp[0], qy = qp[1], qz = qp[2];

        float d0 = 3.4e38f, d1 = 3.4e38f, d2 = 3.4e38f;
        int   i0 = 0x7fffffff, i1 = 0x7fffffff, i2 = 0x7fffffff;
        for (int i = lane; i < N1; i += 32) {
            const float dx = qx - sx[3*i];
            const float dy = qy - sx[3*i+1];
            const float dz = qz - sx[3*i+2];
            const float d  = fmaf(dx, dx, fmaf(dy, dy, dz * dz));
            if (d < d2) {
                if (d < d1) {
                    d2 = d1; i2 = i1;
                    if (d < d0) { d1 = d0; i1 = i0; d0 = d; i0 = i; }
                    else        { d1 = d;  i1 = i; }
                } else { d2 = d; i2 = i; }
            }
        }
        for (int off = 16; off; off >>= 1) {
            float e0 = __shfl_xor_sync(0xffffffffu, d0, off);
            float e1 = __shfl_xor_sync(0xffffffffu, d1, off);
            float e2 = __shfl_xor_sync(0xffffffffu, d2, off);
            int   j0 = __shfl_xor_sync(0xffffffffu, i0, off);
            int   j1 = __shfl_xor_sync(0xffffffffu, i1, off);
            int   j2 = __shfl_xor_sync(0xffffffffu, i2, off);
            float r0, r1, r2; int s0, s1, s2;
            #pragma unroll
            for (int t = 0; t < 3; ++t) {
                const bool takeA = (d0 < e0) || (d0 == e0 && i0 < j0);
                float rv; int ri;
                if (takeA) { rv = d0; ri = i0; d0 = d1; i0 = i1; d1 = d2; i1 = i2; d2 = 3.4e38f; i2 = 0x7fffffff; }
                else       { rv = e0; ri = j0; e0 = e1; j0 = j1; e1 = e2; j1 = j2; e2 = 3.4e38f; j2 = 0x7fffffff; }
                if (t == 0) { r0 = rv; s0 = ri; }
                else if (t == 1) { r1 = rv; s1 = ri; }
                else { r2 = rv; s2 = ri; }
            }
            d0 = r0; d1 = r1; d2 = r2; i0 = s0; i1 = s1; i2 = s2;
        }

        float w0 = 1.0f / (d0 + F32_EPS);
        float w1 = 1.0f / (d1 + F32_EPS);
        float w2 = 1.0f / (d2 + F32_EPS);
        const float inv_sum = 1.0f / (w0 + w1 + w2);
        w0 *= inv_sum; w1 *= inv_sum; w2 *= inv_sum;

        const float4* r0p = (const float4*)(f1b + (size_t)i0 * D1);
        const float4* r1p = (const float4*)(f1b + (size_t)i1 * D1);
        const float4* r2p = (const float4*)(f1b + (size_t)i2 * D1);
        const size_t rowoff = ((size_t)b * NP + j) * DIN;
        uint2* xh = (uint2*)(g_xh + rowoff);
        uint2* xl = (uint2*)(g_xl + rowoff);
        for (int c = lane; c < D1 / 4; c += 32) {
            const float4 a = r0p[c], bb = r1p[c], cc = r2p[c];
            float4 o;
            o.x = w0*a.x + w1*bb.x + w2*cc.x;
            o.y = w0*a.y + w1*bb.y + w2*cc.y;
            o.z = w0*a.z + w1*bb.z + w2*cc.z;
            o.w = w0*a.w + w1*bb.w + w2*cc.w;
            uint2 hi, lo;
            hi.x = pack2(o.x, o.y, lo.x);
            hi.y = pack2(o.z, o.w, lo.y);
            xh[c] = hi; xl[c] = lo;
        }
        const float4* ff2 = (const float4*)(f2 + ((size_t)b * NP + j) * D2);
        uint2* xh2 = (uint2*)(g_xh + rowoff + D1);
        uint2* xl2 = (uint2*)(g_xl + rowoff + D1);
        for (int c = lane; c < D2 / 4; c += 32) {
            const float4 v = ff2[c];
            uint2 hi, lo;
            hi.x = pack2(v.x, v.y, lo.x);
            hi.y = pack2(v.z, v.w, lo.y);
            xh2[c] = hi; xl2[c] = lo;
        }
    }
}

// ---------------------------------------------------------------------------
// Split W1 and W2 into bf16 hi/lo (one launch).
__global__ __launch_bounds__(256) void conv_w_kernel(
    const float* __restrict__ W1, const float* __restrict__ W2)
{
    const int i = blockIdx.x * 256 + threadIdx.x;   // float4 index
    constexpr int N1F4 = HID * DIN / 4;             // 24576
    constexpr int N2F4 = HID * HID / 4;             // 16384
    if (i >= N1F4 + N2F4) return;
    float4 v; uint2* ph; uint2* pl;
    if (i < N1F4) {
        v = ((const float4*)W1)[i];
        ph = (uint2*)g_w1h + i; pl = (uint2*)g_w1l + i;
    } else {
        v = ((const float4*)W2)[i - N1F4];
        ph = (uint2*)g_w2h + (i - N1F4); pl = (uint2*)g_w2l + (i - N1F4);
    }
    uint2 hi, lo;
    hi.x = pack2(v.x, v.y, lo.x);
    hi.y = pack2(v.z, v.w, lo.y);
    *ph = hi; *pl = lo;
}

// ---------------------------------------------------------------------------
// bf16 split-precision mma.sync GEMM, 3-stage cp.async pipeline.
// out[m][n] = sum_k A[m][k] * W[n][k] + bias[n]
// BM=128, BN=128, BK=32; 8 warps (4 m x 2 n), warp tile 32x64.
// 3 passes: Ah*Wh + Ah*Wl + Al*Wh (fp32 accum); dropped Al*Wl ~2^-18.
// SMEM per stage (32 KB): Ah[128x64B] @0, Al @8192, Bh[128x64B] @16384,
// Bl @24576. Three stages = 96 KB dynamic; 2 CTAs/SM.

#define STG 32768u

template<int K, int LAYER>
__global__ __launch_bounds__(256, 2) void gemm_mma_kernel(
    const float* __restrict__ bias, float* __restrict__ out_ext)
{
    extern __shared__ char smem[];
    __shared__ float csum[128], csq[128];
    const uint32_t sb = smem_u32(smem);
    const int tid = threadIdx.x, lane = tid & 31, warp = tid >> 5;
    const int wm = warp & 3, wn = warp >> 2;
    const int n0 = blockIdx.x * 128;    // n-major grid: A m-tile reused via L2
    const int m0 = blockIdx.y * 128;

    const __nv_bfloat16* Ah = (LAYER == 0) ? g_xh  : g_yh;
    const __nv_bfloat16* Al = (LAYER == 0) ? g_xl  : g_yl;
    const __nv_bfloat16* Bh = (LAYER == 0) ? g_w1h : g_w2h;
    const __nv_bfloat16* Bl = (LAYER == 0) ? g_w1l : g_w2l;
    float* outp = (LAYER == 0) ? g_y : out_ext;
    constexpr int NKT = K / 32;

    if (tid < 128) { csum[tid] = 0.0f; csq[tid] = 0.0f; }

    float acc[2][8][4];
    #pragma unroll
    for (int i = 0; i < 2; ++i)
        #pragma unroll
        for (int j = 0; j < 8; ++j)
            #pragma unroll
            for (int v = 0; v < 4; ++v) acc[i][j][v] = 0.0f;

    // stage loader: 2 threads/row, each 2x16B chunks; 8 cp16 per thread
    const int lrow = tid >> 1, lc0 = (tid & 1) * 2;
    auto load_stage = [&](int buf, int k0) {
        const uint32_t st = sb + buf * STG;
        #pragma unroll
        for (int c = 0; c < 2; ++c) {
            const uint32_t so = sw64((uint32_t)(lrow * 64 + (lc0 + c) * 16));
            const size_t ga = (size_t)(m0 + lrow) * K + k0 + (lc0 + c) * 8;
            const size_t gb = (size_t)(n0 + lrow) * K + k0 + (lc0 + c) * 8;
            cp16(st + so,           Ah + ga);
            cp16(st + 8192u  + so,  Al + ga);
            cp16(st + 16384u + so,  Bh + gb);
            cp16(st + 24576u + so,  Bl + gb);
        }
        asm volatile("cp.async.commit_group;" ::: "memory");
    };

    load_stage(0, 0);
    load_stage(1, 32);

    // ldmatrix lane addressing
    const int rowadd = (lane & 7) + ((lane >> 3) & 1) * 8;
    const int kadd = (lane >> 4) * 16;               // bytes

    int buf = 0;
    for (int kt = 0; kt < NKT; ++kt) {
        if (kt == NKT - 1) asm volatile("cp.async.wait_group 0;" ::: "memory");
        else               asm volatile("cp.async.wait_group 1;" ::: "memory");
        __syncthreads();
        if (kt + 2 < NKT) {
            int nb = buf + 2; if (nb >= 3) nb -= 3;
            load_stage(nb, (kt + 2) * 32);
        }

        const uint32_t st = sb + buf * STG;
        #pragma unroll
        for (int ks = 0; ks < 2; ++ks) {
            const int kb = ks * 32 + kadd;           // byte offset of k16 step
            unsigned ah[2][4], al[2][4], bh[4][4], bl[4][4];
            #pragma unroll
            for (int i = 0; i < 2; ++i) {
                const uint32_t off = sw64((uint32_t)((wm * 32 + i * 16 + rowadd) * 64 + kb));
                ldsm4(ah[i], st + off);
                ldsm4(al[i], st + 8192u + off);
            }
            #pragma unroll
            for (int b = 0; b < 4; ++b) {
                const uint32_t off = sw64((uint32_t)((wn * 64 + b * 16 + rowadd) * 64 + kb));
                ldsm4(bh[b], st + 16384u + off);
                ldsm4(bl[b], st + 24576u + off);
            }
            #pragma unroll
            for (int i = 0; i < 2; ++i)
                #pragma unroll
                for (int j = 0; j < 8; ++j) {
                    const int blk = j >> 1, s = j & 1;
                    mma_b(acc[i][j], ah[i], bh[blk][s], bh[blk][s + 2]);
                    mma_b(acc[i][j], ah[i], bl[blk][s], bl[blk][s + 2]);
                    mma_b(acc[i][j], al[i], bh[blk][s], bh[blk][s + 2]);
                }
        }
        if (++buf >= 3) buf = 0;
    }

    // --- Epilogue: bias, store fp32, per-channel stats ---
    const int g = lane >> 2, t = lane & 3;
    float ps[8][2], pq[8][2];
    #pragma unroll
    for (int j = 0; j < 8; ++j) { ps[j][0]=ps[j][1]=pq[j][0]=pq[j][1]=0.0f; }

    #pragma unroll
    for (int j = 0; j < 8; ++j) {
        const int col = n0 + wn * 64 + j * 8 + 2 * t;
        const float b0 = __ldg(bias + col), b1 = __ldg(bias + col + 1);
        #pragma unroll
        for (int i = 0; i < 2; ++i) {
            const int row = m0 + wm * 32 + i * 16 + g;
            float v0 = acc[i][j][0] + b0;
            float v1 = acc[i][j][1] + b1;
            float v2 = acc[i][j][2] + b0;
            float v3 = acc[i][j][3] + b1;
            *(float2*)(outp + (size_t)row * HID + col)       = make_float2(v0, v1);
            *(float2*)(outp + (size_t)(row + 8) * HID + col) = make_float2(v2, v3);
            ps[j][0] += v0 + v2;  pq[j][0] += v0*v0 + v2*v2;
            ps[j][1] += v1 + v3;  pq[j][1] += v1*v1 + v3*v3;
        }
    }
    __syncthreads();
    #pragma unroll
    for (int j = 0; j < 8; ++j) {
        const int l = wn * 64 + j * 8 + 2 * t;
        atomicAdd(&csum[l],     ps[j][0]);
        atomicAdd(&csum[l + 1], ps[j][1]);
        atomicAdd(&csq[l],      pq[j][0]);
        atomicAdd(&csq[l + 1],  pq[j][1]);
    }
    __syncthreads();
    if (tid < 128) {
        const int SOFF = LAYER * 2 * HID;
        atomicAdd(&g_stats[SOFF + n0 + tid],       csum[tid]);
        atomicAdd(&g_stats[SOFF + HID + n0 + tid], csq[tid]);
    }
}

// ---------------------------------------------------------------------------
// Apply layer-1 BN (finalized inline from g_stats) + ReLU to g_y, emit
// split bf16 for GEMM2. 2048 blocks x 8 float4 per thread.
__global__ __launch_bounds__(256) void conv_y_kernel(
    const float* __restrict__ g, const float* __restrict__ beta)
{
    __shared__ float sa[HID], ss[HID];
    const int tid = threadIdx.x;
    {
        const float invM = 1.0f / (float)MTOT;
        const float sum = g_stats[tid];
        const float sq  = g_stats[HID + tid];
        const float mu  = sum * invM;
        const float var = sq * invM - mu * mu;
        const float a   = rsqrtf(var + BN_EPS) * g[tid];
        sa[tid] = a; ss[tid] = beta[tid] - mu * a;
    }
    __syncthreads();

    const int base = blockIdx.x * 256 * 8;
    #pragma unroll
    for (int r = 0; r < 8; ++r) {
        const int i = base + r * 256 + tid;          // float4 index
        float4 v = ((const float4*)g_y)[i];
        const int c = (i * 4) & (HID - 1);
        const float4 a = *(const float4*)&sa[c];
        const float4 s = *(const float4*)&ss[c];
        v.x = fmaxf(fmaf(v.x, a.x, s.x), 0.0f);
        v.y = fmaxf(fmaf(v.y, a.y, s.y), 0.0f);
        v.z = fmaxf(fmaf(v.z, a.z, s.z), 0.0f);
        v.w = fmaxf(fmaf(v.w, a.w, s.w), 0.0f);
        uint2 hi, lo;
        hi.x = pack2(v.x, v.y, lo.x);
        hi.y = pack2(v.z, v.w, lo.y);
        ((uint2*)g_yh)[i] = hi;
        ((uint2*)g_yl)[i] = lo;
    }
}

// ---------------------------------------------------------------------------
// Final BN (layer 2, finalized inline) + ReLU on the output, in place.
__global__ __launch_bounds__(256) void final_norm_kernel(
    float* __restrict__ out, const float* __restrict__ g,
    const float* __restrict__ beta)
{
    __shared__ float sa[HID], ss[HID];
    const int tid = threadIdx.x;
    {
        const float invM = 1.0f / (float)MTOT;
        const float sum = g_stats[2 * HID + tid];
        const float sq  = g_stats[3 * HID + tid];
        const float mu  = sum * invM;
        const float var = sq * invM - mu * mu;
        const float a   = rsqrtf(var + BN_EPS) * g[tid];
        sa[tid] = a; ss[tid] = beta[tid] - mu * a;
    }
    __syncthreads();

    const int base = blockIdx.x * 256 * 8;
    #pragma unroll
    for (int r = 0; r < 8; ++r) {
        const int i = base + r * 256 + tid;          // float4 index
        float4 v = ((float4*)out)[i];
        const int c = (i * 4) & (HID - 1);
        const float4 a = *(const float4*)&sa[c];
        const float4 s = *(const float4*)&ss[c];
        v.x = fmaxf(fmaf(v.x, a.x, s.x), 0.0f);
        v.y = fmaxf(fmaf(v.y, a.y, s.y), 0.0f);
        v.z = fmaxf(fmaf(v.z, a.z, s.z), 0.0f);
        v.w = fmaxf(fmaf(v.w, a.w, s.w), 0.0f);
        ((float4*)out)[i] = v;
    }
}

// ---------------------------------------------------------------------------
extern "C" void kernel_launch(void* const* d_in, const int* in_sizes, int n_in,
                              void* d_out, int out_size)
{
    const float* xyz1  = (const float*)d_in[0];
    const float* xyz2  = (const float*)d_in[1];
    const float* f1    = (const float*)d_in[2];
    const float* f2    = (const float*)d_in[3];
    const float* W1    = (const float*)d_in[4];
    const float* b1    = (const float*)d_in[5];
    const float* g1    = (const float*)d_in[6];
    const float* beta1 = (const float*)d_in[7];
    const float* W2    = (const float*)d_in[8];
    const float* b2    = (const float*)d_in[9];
    const float* g2    = (const float*)d_in[10];
    const float* beta2 = (const float*)d_in[11];
    float* out = (float*)d_out;

    cudaFuncSetAttribute(gemm_mma_kernel<DIN, 0>,
                         cudaFuncAttributeMaxDynamicSharedMemorySize, 3 * STG);
    cudaFuncSetAttribute(gemm_mma_kernel<HID, 1>,
                         cudaFuncAttributeMaxDynamicSharedMemorySize, 3 * STG);

    interp_kernel<<<dim3(NP / 32, BATCH), 256>>>(xyz1, xyz2, f1, f2);
    conv_w_kernel<<<(HID * DIN / 4 + HID * HID / 4 + 255) / 256, 256>>>(W1, W2);

    gemm_mma_kernel<DIN, 0><<<dim3(HID / 128, MTOT / 128), 256, 3 * STG>>>(b1, nullptr);
    conv_y_kernel<<<MTOT * HID / 4 / (256 * 8), 256>>>(g1, beta1);

    gemm_mma_kernel<HID, 1><<<dim3(HID / 128, MTOT / 128), 256, 3 * STG>>>(b2, out);
    final_norm_kernel<<<MTOT * HID / 4 / (256 * 8), 256>>>(out, g2, beta2);
}